// round 13
// baseline (speedup 1.0000x reference)
#include <cuda_runtime.h>
#include <math.h>

// Problem constants
#define BB      128
#define CC      3
#define HH      224
#define PN      14          // patches per side
#define PS      16          // patch size
#define NP      196         // PN*PN
#define DD      768
#define NC      1000
#define TOPK    20
#define KDIM    588         // C*NP
#define NPART   16          // partials for patch_grad reduction (8 batches each)
#define SPLITK  4
#define KSEG    147         // KDIM / SPLITK

// -------- scratch (device globals; no runtime allocation) --------
__device__ float g_patch_partial[NP * NPART];
__device__ float g_attack_pooled[KDIM];          // c*196 + px*14 + py
__device__ float g_pooled_in[BB * KDIM];         // [b][c*196 + p]
__device__ float g_logits_part[SPLITK][BB * NC]; // split-K partials
__device__ float g_v[NC];                        // batch-independent mask term
__device__ float g_probs_fallback[BB * NC];
__device__ float g_ce[BB];
__device__ int   g_ctr;                          // last-softmax-row counter
__device__ int   g_done;                         // gemm+v done counter

// ============================================================================
// Kernel 1 (fused, HBM-bound): pool inputs+attack_w 16x16 means AND reduce
// patch_grad over (batch, dim). Two independent 77MB streams in one grid.
// At 75.6% DRAM this is ~8% off the practical cap -- leave as is.
// Also resets both counters (deterministic per-call init).
// ============================================================================
#define POOL_BLOCKS (129 * CC * PN)   // 5418
#define GRAD_BLOCKS (NP * NPART)      // 3136

__global__ void k1_pool_and_reduce(const float* __restrict__ inputs,
                                   const float* __restrict__ attack_w,
                                   const float* __restrict__ patch_grad) {
    int blk = blockIdx.x;
    int t   = threadIdx.x;   // 0..223

    if (blk == 0 && t == 0) { g_ctr = 0; g_done = 0; }

    if (blk < POOL_BLOCKS) {
        int bb  = blk / (CC * PN);
        int rem = blk % (CC * PN);
        int c   = rem / PN;
        int px  = rem % PN;
        const float* src = (bb < BB)
            ? inputs   + ((size_t)(bb * CC + c) * HH + px * PS) * HH
            : attack_w + ((size_t)c * HH + px * PS) * HH;
        float acc = 0.f;
        #pragma unroll
        for (int r = 0; r < PS; ++r) acc += src[r * HH + t];
        #pragma unroll
        for (int off = 8; off > 0; off >>= 1)
            acc += __shfl_down_sync(0xffffffffu, acc, off, 16);
        if ((t & 15) == 0) {
            int iy  = t >> 4;
            float v = acc * (1.0f / 256.0f);
            int idx = c * NP + px * PN + iy;
            if (bb < BB) g_pooled_in[bb * KDIM + idx] = v;
            else         g_attack_pooled[idx]          = v;
        }
    } else {
        int gid  = blk - POOL_BLOCKS;
        int p    = gid >> 4;
        int part = gid & 15;
        int b0   = part * (BB / NPART);
        float acc = 0.f;
        if (t < DD / 4) {
            #pragma unroll
            for (int bi = 0; bi < BB / NPART; ++bi) {
                const float4 v = reinterpret_cast<const float4*>(
                    patch_grad + ((size_t)(b0 + bi) * NP + p) * DD)[t];
                acc += (v.x + v.y) + (v.z + v.w);
            }
        }
        #pragma unroll
        for (int off = 16; off > 0; off >>= 1)
            acc += __shfl_down_sync(0xffffffffu, acc, off);
        __shared__ float ws[7];
        if ((t & 31) == 0) ws[t >> 5] = acc;
        __syncthreads();
        if (t == 0) {
            float s = 0.f;
            #pragma unroll
            for (int w = 0; w < 7; ++w) s += ws[w];
            g_patch_partial[p * NPART + part] = s;
        }
    }
}

// ============================================================================
// Kernel 3 (single fused launch, 1D grid of 392 blocks x 128 threads):
//  bid <  256: split-K SGEMM  logits_part[z] = pooled_in @ w_cls slice
//              BM=32 x BN=64, 4m x 4n per thread, KT=49 x 3 per z-slice.
//              sA filled m-fast (conflict-free smem stores; A reads are
//              uncoalesced but hit L2-resident pooled_in -- negligible).
//  bid < 264:  8 v-blocks: top-k mask + masked GEMV (batch-independent term)
//  bid >= 264: 128 softmax rows. Spin on g_done (all 264 producer blocks are
//              co-resident with them -> deadlock-free), then softmax + CE,
//              with the final loss from a deterministic last-row reduction.
// ============================================================================
#define BM 32
#define BN 64
#define KT 49
#define GEMM_BLOCKS 256           // 16 n-tiles * 4 m-tiles * 4 z
#define VB          8
#define PROD_BLOCKS (GEMM_BLOCKS + VB)

__device__ __forceinline__ float warpMax(float v) {
    #pragma unroll
    for (int o = 16; o > 0; o >>= 1) v = fmaxf(v, __shfl_xor_sync(0xffffffffu, v, o));
    return v;
}
__device__ __forceinline__ float warpSum(float v) {
    #pragma unroll
    for (int o = 16; o > 0; o >>= 1) v += __shfl_xor_sync(0xffffffffu, v, o);
    return v;
}

__global__ void k3_fused(const float* __restrict__ w_cls,
                         const int* __restrict__ targets,
                         float* __restrict__ pdst,
                         float* __restrict__ out, int loss_idx) {
    int bid = blockIdx.x;
    int t   = threadIdx.x;   // 0..127

    if (bid < GEMM_BLOCKS) {
        __shared__ float sA[KT][BM];   // 6.1 KB
        __shared__ float sW[KT][BN];   // 12.25 KB
        int n_idx = bid & 15;
        int m_idx = (bid >> 4) & 3;
        int z     = bid >> 6;
        int n0 = n_idx * BN;
        int m0 = m_idx * BM;
        int kb = z * KSEG;
        int tn4 = (t & 15) * 4;   // n-group
        int tm4 = (t >> 4) * 4;   // m-group (8 groups x 4 rows)
        float acc[4][4];
        #pragma unroll
        for (int r = 0; r < 4; ++r)
            #pragma unroll
            for (int c = 0; c < 4; ++c) acc[r][c] = 0.f;

        #pragma unroll
        for (int kt = 0; kt < KSEG / KT; ++kt) {
            int k0 = kb + kt * KT;
            // sA fill: m-fast -> conflict-free smem stores
            #pragma unroll
            for (int i = t; i < BM * KT; i += 128) {
                int k = i >> 5;         // i / 32
                int m = i & 31;
                sA[k][m] = g_pooled_in[(m0 + m) * KDIM + k0 + k];
            }
            #pragma unroll
            for (int i = t; i < KT * BN; i += 128) {
                int kk = i >> 6;
                int n  = i & 63;
                int gn = n0 + n;
                sW[kk][n] = (gn < NC) ? w_cls[(size_t)(k0 + kk) * NC + gn] : 0.0f;
            }
            __syncthreads();
            #pragma unroll 7
            for (int k = 0; k < KT; ++k) {
                float4 a = *(const float4*)&sA[k][tm4];
                float4 w = *(const float4*)&sW[k][tn4];
                acc[0][0] += a.x * w.x; acc[0][1] += a.x * w.y;
                acc[0][2] += a.x * w.z; acc[0][3] += a.x * w.w;
                acc[1][0] += a.y * w.x; acc[1][1] += a.y * w.y;
                acc[1][2] += a.y * w.z; acc[1][3] += a.y * w.w;
                acc[2][0] += a.z * w.x; acc[2][1] += a.z * w.y;
                acc[2][2] += a.z * w.z; acc[2][3] += a.z * w.w;
                acc[3][0] += a.w * w.x; acc[3][1] += a.w * w.y;
                acc[3][2] += a.w * w.z; acc[3][3] += a.w * w.w;
            }
            __syncthreads();
        }
        float* dst = g_logits_part[z];
        #pragma unroll
        for (int r = 0; r < 4; ++r) {
            int m = m0 + tm4 + r;
            #pragma unroll
            for (int j = 0; j < 4; ++j) {
                int n = n0 + tn4 + j;
                if (n < NC) dst[m * NC + n] = acc[r][j];
            }
        }
        __syncthreads();
        if (t == 0) { __threadfence(); atomicAdd(&g_done, 1); }
    } else if (bid < PROD_BLOCKS) {
        // ---- v-block: top-k mask + masked GEMV ----
        int vb = bid - GEMM_BLOCKS;   // 0..7
        __shared__ float         sv[NP];
        __shared__ unsigned char smask[NP];
        __shared__ int           plist[TOPK];
        for (int i = t; i < NP; i += 128) {
            float v = 0.f;
            #pragma unroll
            for (int q = 0; q < NPART; ++q) v += g_patch_partial[i * NPART + q];
            sv[i] = v;
        }
        __syncthreads();
        for (int i = t; i < NP; i += 128) {
            float v = sv[i];
            int rank = 0;
            for (int j = 0; j < NP; ++j) {
                float u = sv[j];
                rank += (u > v) || (u == v && j < i);
            }
            smask[i] = (rank < TOPK) ? 1 : 0;
        }
        __syncthreads();
        if (t == 0) {
            int cnt = 0;
            for (int p = 0; p < NP; ++p)
                if (smask[p] && cnt < TOPK) plist[cnt++] = p;
        }
        __syncthreads();
        int n = vb * 125 + t;          // 8 blocks x 125 cols = 1000
        if (t < 125) {
            float acc = 0.f;
            #pragma unroll 2
            for (int i = 0; i < TOPK; ++i) {
                int p = plist[i];
                #pragma unroll
                for (int c = 0; c < CC; ++c) {
                    int k = c * NP + p;
                    acc += g_attack_pooled[k] * w_cls[(size_t)k * NC + n];
                }
            }
            g_v[n] = acc;
        }
        __syncthreads();
        if (t == 0) { __threadfence(); atomicAdd(&g_done, 1); }
    } else {
        // ---- softmax + CE for one batch row; waits for all producers ----
        int b = bid - PROD_BLOCKS;     // 0..127
        int w = t >> 5;
        __shared__ float red[4];
        __shared__ float ptgt;
        __shared__ int   slast;

        if (t == 0) {
            while (atomicAdd(&g_done, 0) < PROD_BLOCKS) __nanosleep(128);
        }
        __syncthreads();
        __threadfence();

        float l[8];
        float m = -INFINITY;
        #pragma unroll
        for (int i = 0; i < 8; ++i) {
            int j = t + i * 128;
            if (j < NC) {
                size_t o = (size_t)b * NC + j;
                l[i] = ((g_logits_part[0][o] + g_logits_part[1][o])
                      + (g_logits_part[2][o] + g_logits_part[3][o])) + g_v[j];
                m = fmaxf(m, l[i]);
            } else l[i] = -INFINITY;
        }
        m = warpMax(m);
        if ((t & 31) == 0) red[w] = m;
        __syncthreads();
        float rowmax = fmaxf(fmaxf(red[0], red[1]), fmaxf(red[2], red[3]));
        __syncthreads();

        float e[8]; float ssum = 0.f;
        #pragma unroll
        for (int i = 0; i < 8; ++i) {
            int j = t + i * 128;
            e[i] = (j < NC) ? __expf(l[i] - rowmax) : 0.f;
            ssum += e[i];
        }
        ssum = warpSum(ssum);
        if ((t & 31) == 0) red[w] = ssum;
        __syncthreads();
        float tot = ((red[0] + red[1]) + (red[2] + red[3]));
        float inv = 1.0f / tot;
        __syncthreads();

        int tgt = targets[b];
        float s2 = 0.f;
        #pragma unroll
        for (int i = 0; i < 8; ++i) {
            int j = t + i * 128;
            if (j < NC) {
                float p = e[i] * inv;
                pdst[(size_t)b * NC + j] = p;
                if (j == tgt) ptgt = p;
                // exp(p), p in (0,1]: degree-4 Taylor (FMA pipe, not MUFU)
                float q = fmaf(p, 1.0f / 24.0f, 1.0f / 6.0f);
                q = fmaf(p, q, 0.5f);
                q = fmaf(p, q, 1.0f);
                q = fmaf(p, q, 1.0f);
                s2 += q;
            }
        }
        s2 = warpSum(s2);
        if ((t & 31) == 0) red[w] = s2;
        __syncthreads();
        if (t == 0) {
            float tot2 = ((red[0] + red[1]) + (red[2] + red[3]));
            g_ce[b] = logf(tot2) - ptgt;
            __threadfence();
            int done = atomicAdd(&g_ctr, 1);
            slast = (done == BB - 1) ? 1 : 0;
        }
        __syncthreads();
        if (slast && t < 32 && loss_idx >= 0) {
            __threadfence();
            float s = 0.f;
            #pragma unroll
            for (int i = 0; i < 4; ++i) s += g_ce[t * 4 + i];
            #pragma unroll
            for (int off = 16; off > 0; off >>= 1)
                s += __shfl_down_sync(0xffffffffu, s, off);
            if (t == 0) out[loss_idx] = -(s * (1.0f / BB));
        }
    }
}

// ============================================================================
extern "C" void kernel_launch(void* const* d_in, const int* in_sizes, int n_in,
                              void* d_out, int out_size) {
    const float* inputs     = (const float*)d_in[0];   // [128,3,224,224]
    const float* patch_grad = (const float*)d_in[1];   // [128,196,768]
    const float* attack_w   = (const float*)d_in[2];   // [3,224,224]
    const float* w_cls      = (const float*)d_in[3];   // [588,1000]
    const int*   targets    = (const int*)d_in[4];     // [128]
    float* out = (float*)d_out;

    (void)in_sizes; (void)n_in;

    float* pdst = out;
    if (out_size < BB * NC) {
        float* fb = nullptr;
        cudaGetSymbolAddress((void**)&fb, g_probs_fallback);
        pdst = fb;
    }
    int loss_idx = -1;
    if (out_size >= BB * NC + 1)      loss_idx = BB * NC;
    else if (out_size == 1)           loss_idx = 0;

    k1_pool_and_reduce<<<POOL_BLOCKS + GRAD_BLOCKS, 224>>>(inputs, attack_w, patch_grad);
    k3_fused<<<PROD_BLOCKS + BB, 128>>>(w_cls, targets, pdst, out, loss_idx);
}

// round 14
// speedup vs baseline: 1.0737x; 1.0737x over previous
#include <cuda_runtime.h>
#include <math.h>

// Problem constants
#define BB      128
#define CC      3
#define HH      224
#define PN      14          // patches per side
#define PS      16          // patch size
#define NP      196         // PN*PN
#define DD      768
#define NC      1000
#define TOPK    20
#define KDIM    588         // C*NP
#define NPART   16          // partials for patch_grad reduction (8 batches each)
#define SPLITK  4
#define KSEG    147         // KDIM / SPLITK

// -------- scratch (device globals; no runtime allocation) --------
__device__ float g_patch_partial[NP * NPART];
__device__ float g_attack_pooled[KDIM];          // c*196 + px*14 + py
__device__ float g_pooled_in[BB * KDIM];         // [b][c*196 + p]
__device__ float g_logits_part[SPLITK][BB * NC]; // split-K partials
__device__ float g_v[NC];                        // batch-independent mask term
__device__ float g_probs_fallback[BB * NC];
__device__ float g_ce[BB];
__device__ int   g_ctr;                          // last-softmax-row counter
__device__ int   g_done;                         // gemm+v done counter

// ============================================================================
// Kernel 1 (fused, HBM-bound, measured 26.5us @ 75.6% DRAM): pool
// inputs+attack_w 16x16 means AND reduce patch_grad over (batch, dim).
// Also resets both counters (deterministic per-call init).
// ============================================================================
#define POOL_BLOCKS (129 * CC * PN)   // 5418
#define GRAD_BLOCKS (NP * NPART)      // 3136

__global__ void k1_pool_and_reduce(const float* __restrict__ inputs,
                                   const float* __restrict__ attack_w,
                                   const float* __restrict__ patch_grad) {
    int blk = blockIdx.x;
    int t   = threadIdx.x;   // 0..223

    if (blk == 0 && t == 0) { g_ctr = 0; g_done = 0; }

    if (blk < POOL_BLOCKS) {
        int bb  = blk / (CC * PN);
        int rem = blk % (CC * PN);
        int c   = rem / PN;
        int px  = rem % PN;
        const float* src = (bb < BB)
            ? inputs   + ((size_t)(bb * CC + c) * HH + px * PS) * HH
            : attack_w + ((size_t)c * HH + px * PS) * HH;
        float acc = 0.f;
        #pragma unroll
        for (int r = 0; r < PS; ++r) acc += src[r * HH + t];
        #pragma unroll
        for (int off = 8; off > 0; off >>= 1)
            acc += __shfl_down_sync(0xffffffffu, acc, off, 16);
        if ((t & 15) == 0) {
            int iy  = t >> 4;
            float v = acc * (1.0f / 256.0f);
            int idx = c * NP + px * PN + iy;
            if (bb < BB) g_pooled_in[bb * KDIM + idx] = v;
            else         g_attack_pooled[idx]          = v;
        }
    } else {
        int gid  = blk - POOL_BLOCKS;
        int p    = gid >> 4;
        int part = gid & 15;
        int b0   = part * (BB / NPART);
        float acc = 0.f;
        if (t < DD / 4) {
            #pragma unroll
            for (int bi = 0; bi < BB / NPART; ++bi) {
                const float4 v = reinterpret_cast<const float4*>(
                    patch_grad + ((size_t)(b0 + bi) * NP + p) * DD)[t];
                acc += (v.x + v.y) + (v.z + v.w);
            }
        }
        #pragma unroll
        for (int off = 16; off > 0; off >>= 1)
            acc += __shfl_down_sync(0xffffffffu, acc, off);
        __shared__ float ws[7];
        if ((t & 31) == 0) ws[t >> 5] = acc;
        __syncthreads();
        if (t == 0) {
            float s = 0.f;
            #pragma unroll
            for (int w = 0; w < 7; ++w) s += ws[w];
            g_patch_partial[p * NPART + part] = s;
        }
    }
}

// ============================================================================
// Kernel 2 (single fused launch, 648 blocks x 128 threads):
//  bid <  512: split-K SGEMM  logits_part[z] = pooled_in @ w_cls slice.
//              R12-proven internals: BM=16 x BN=64, KT=49, k-fast COALESCED
//              fills, 2m x 4n thread tile (~40 regs).
//  bid <  520: 8 v-blocks: top-k mask + masked GEMV (batch-independent term;
//              stride loops since NP=196 > 128 threads).
//  bid >= 520: 128 softmax rows. Spin on g_done (deadlock-free: producers
//              never wait, so queued consumers always eventually run),
//              then softmax + CE + deterministic last-row loss.
// ============================================================================
#define BM 16
#define BN 64
#define KT 49
#define GEMM_BLOCKS 512           // 16 n-tiles * 8 m-tiles * 4 z
#define VB          8
#define PROD_BLOCKS (GEMM_BLOCKS + VB)

__device__ __forceinline__ float warpMax(float v) {
    #pragma unroll
    for (int o = 16; o > 0; o >>= 1) v = fmaxf(v, __shfl_xor_sync(0xffffffffu, v, o));
    return v;
}
__device__ __forceinline__ float warpSum(float v) {
    #pragma unroll
    for (int o = 16; o > 0; o >>= 1) v += __shfl_xor_sync(0xffffffffu, v, o);
    return v;
}

__global__ void k2_fused(const float* __restrict__ w_cls,
                         const int* __restrict__ targets,
                         float* __restrict__ pdst,
                         float* __restrict__ out, int loss_idx) {
    int bid = blockIdx.x;
    int t   = threadIdx.x;   // 0..127

    if (bid < GEMM_BLOCKS) {
        __shared__ float sA[KT][BM];
        __shared__ float sW[KT][BN];
        int n0 = (bid & 15) * BN;
        int m0 = ((bid >> 4) & 7) * BM;
        int kb = (bid >> 7) * KSEG;
        int tn = t & 15;          // n-group (4 cols)
        int tm = t >> 4;          // m-group (2 rows)
        float acc[2][4] = {{0.f, 0.f, 0.f, 0.f}, {0.f, 0.f, 0.f, 0.f}};

        #pragma unroll
        for (int kt = 0; kt < KSEG / KT; ++kt) {
            int k0 = kb + kt * KT;
            // k-fast fill: consecutive threads -> consecutive k (coalesced)
            #pragma unroll
            for (int i = t; i < BM * KT; i += 128) {
                int m = i / KT;
                int k = i - m * KT;
                sA[k][m] = g_pooled_in[(m0 + m) * KDIM + k0 + k];
            }
            #pragma unroll
            for (int i = t; i < KT * BN; i += 128) {
                int kk = i >> 6;
                int n  = i & 63;
                int gn = n0 + n;
                sW[kk][n] = (gn < NC) ? w_cls[(size_t)(k0 + kk) * NC + gn] : 0.0f;
            }
            __syncthreads();
            #pragma unroll 7
            for (int k = 0; k < KT; ++k) {
                float2 a = *(const float2*)&sA[k][tm * 2];
                float4 w = *(const float4*)&sW[k][tn * 4];
                acc[0][0] += a.x * w.x; acc[0][1] += a.x * w.y;
                acc[0][2] += a.x * w.z; acc[0][3] += a.x * w.w;
                acc[1][0] += a.y * w.x; acc[1][1] += a.y * w.y;
                acc[1][2] += a.y * w.z; acc[1][3] += a.y * w.w;
            }
            __syncthreads();
        }
        float* dst = g_logits_part[bid >> 7];
        #pragma unroll
        for (int r = 0; r < 2; ++r) {
            int m = m0 + tm * 2 + r;
            #pragma unroll
            for (int j = 0; j < 4; ++j) {
                int n = n0 + tn * 4 + j;
                if (n < NC) dst[m * NC + n] = acc[r][j];
            }
        }
        __syncthreads();
        if (t == 0) { __threadfence(); atomicAdd(&g_done, 1); }
    } else if (bid < PROD_BLOCKS) {
        // ---- v-block: top-k mask + masked GEMV ----
        int vb = bid - GEMM_BLOCKS;   // 0..7
        __shared__ float         sv[NP];
        __shared__ unsigned char smask[NP];
        __shared__ int           plist[TOPK];
        for (int i = t; i < NP; i += 128) {
            float v = 0.f;
            #pragma unroll
            for (int q = 0; q < NPART; ++q) v += g_patch_partial[i * NPART + q];
            sv[i] = v;
        }
        __syncthreads();
        // rank-based top-20; ties broken by lower index (jax.lax.top_k order)
        for (int i = t; i < NP; i += 128) {
            float v = sv[i];
            int rank = 0;
            for (int j = 0; j < NP; ++j) {
                float u = sv[j];
                rank += (u > v) || (u == v && j < i);
            }
            smask[i] = (rank < TOPK) ? 1 : 0;
        }
        __syncthreads();
        if (t == 0) {                          // deterministic ascending list
            int cnt = 0;
            for (int p = 0; p < NP; ++p)
                if (smask[p] && cnt < TOPK) plist[cnt++] = p;
        }
        __syncthreads();
        int n = vb * 125 + t;                  // 8 blocks x 125 cols = 1000
        if (t < 125) {
            float acc = 0.f;
            #pragma unroll 2
            for (int i = 0; i < TOPK; ++i) {
                int p = plist[i];
                #pragma unroll
                for (int c = 0; c < CC; ++c) {
                    int k = c * NP + p;
                    acc += g_attack_pooled[k] * w_cls[(size_t)k * NC + n];
                }
            }
            g_v[n] = acc;
        }
        __syncthreads();
        if (t == 0) { __threadfence(); atomicAdd(&g_done, 1); }
    } else {
        // ---- softmax + CE for one batch row; waits for all producers ----
        int b = bid - PROD_BLOCKS;     // 0..127
        int w = t >> 5;
        __shared__ float red[4];
        __shared__ float ptgt;
        __shared__ int   slast;

        if (t == 0) {
            while (atomicAdd(&g_done, 0) < PROD_BLOCKS) __nanosleep(64);
        }
        __syncthreads();
        __threadfence();

        float l[8];
        float m = -INFINITY;
        #pragma unroll
        for (int i = 0; i < 8; ++i) {
            int j = t + i * 128;
            if (j < NC) {
                size_t o = (size_t)b * NC + j;
                l[i] = ((g_logits_part[0][o] + g_logits_part[1][o])
                      + (g_logits_part[2][o] + g_logits_part[3][o])) + g_v[j];
                m = fmaxf(m, l[i]);
            } else l[i] = -INFINITY;
        }
        m = warpMax(m);
        if ((t & 31) == 0) red[w] = m;
        __syncthreads();
        float rowmax = fmaxf(fmaxf(red[0], red[1]), fmaxf(red[2], red[3]));
        __syncthreads();

        float e[8]; float ssum = 0.f;
        #pragma unroll
        for (int i = 0; i < 8; ++i) {
            int j = t + i * 128;
            e[i] = (j < NC) ? __expf(l[i] - rowmax) : 0.f;
            ssum += e[i];
        }
        ssum = warpSum(ssum);
        if ((t & 31) == 0) red[w] = ssum;
        __syncthreads();
        float tot = ((red[0] + red[1]) + (red[2] + red[3]));
        float inv = 1.0f / tot;
        __syncthreads();

        int tgt = targets[b];
        float s2 = 0.f;
        #pragma unroll
        for (int i = 0; i < 8; ++i) {
            int j = t + i * 128;
            if (j < NC) {
                float p = e[i] * inv;
                pdst[(size_t)b * NC + j] = p;
                if (j == tgt) ptgt = p;
                // exp(p), p in (0,1]: degree-4 Taylor (FMA pipe, not MUFU)
                float q = fmaf(p, 1.0f / 24.0f, 1.0f / 6.0f);
                q = fmaf(p, q, 0.5f);
                q = fmaf(p, q, 1.0f);
                q = fmaf(p, q, 1.0f);
                s2 += q;
            }
        }
        s2 = warpSum(s2);
        if ((t & 31) == 0) red[w] = s2;
        __syncthreads();
        if (t == 0) {
            float tot2 = ((red[0] + red[1]) + (red[2] + red[3]));
            g_ce[b] = logf(tot2) - ptgt;
            __threadfence();
            int done = atomicAdd(&g_ctr, 1);
            slast = (done == BB - 1) ? 1 : 0;
        }
        __syncthreads();
        if (slast && t < 32 && loss_idx >= 0) {
            __threadfence();
            float s = 0.f;
            #pragma unroll
            for (int i = 0; i < 4; ++i) s += g_ce[t * 4 + i];
            #pragma unroll
            for (int off = 16; off > 0; off >>= 1)
                s += __shfl_down_sync(0xffffffffu, s, off);
            if (t == 0) out[loss_idx] = -(s * (1.0f / BB));
        }
    }
}

// ============================================================================
extern "C" void kernel_launch(void* const* d_in, const int* in_sizes, int n_in,
                              void* d_out, int out_size) {
    const float* inputs     = (const float*)d_in[0];   // [128,3,224,224]
    const float* patch_grad = (const float*)d_in[1];   // [128,196,768]
    const float* attack_w   = (const float*)d_in[2];   // [3,224,224]
    const float* w_cls      = (const float*)d_in[3];   // [588,1000]
    const int*   targets    = (const int*)d_in[4];     // [128]
    float* out = (float*)d_out;

    (void)in_sizes; (void)n_in;

    float* pdst = out;
    if (out_size < BB * NC) {
        float* fb = nullptr;
        cudaGetSymbolAddress((void**)&fb, g_probs_fallback);
        pdst = fb;
    }
    int loss_idx = -1;
    if (out_size >= BB * NC + 1)      loss_idx = BB * NC;
    else if (out_size == 1)           loss_idx = 0;

    k1_pool_and_reduce<<<POOL_BLOCKS + GRAD_BLOCKS, 224>>>(inputs, attack_w, patch_grad);
    k2_fused<<<PROD_BLOCKS + BB, 128>>>(w_cls, targets, pdst, out, loss_idx);
}

// round 15
// speedup vs baseline: 1.0780x; 1.0040x over previous
#include <cuda_runtime.h>
#include <math.h>

// Problem constants
#define BB      128
#define CC      3
#define HH      224
#define PN      14          // patches per side
#define PS      16          // patch size
#define NP      196         // PN*PN
#define DD      768
#define NC      1000
#define TOPK    20
#define KDIM    588         // C*NP
#define NPART   16          // partials for patch_grad reduction (8 batches each)
#define SPLITK  12
#define KT      49          // KDIM / SPLITK (one smem tile per block)

// -------- scratch (device globals; no runtime allocation) --------
__device__ float g_patch_partial[NP * NPART];
__device__ float g_attack_pooled[KDIM];          // c*196 + px*14 + py
__device__ float g_pooled_in[BB * KDIM];         // [b][c*196 + p]
__device__ float g_logits_part[SPLITK][BB * NC]; // split-K partials (6 MB)
__device__ float g_v[NC];                        // batch-independent mask term
__device__ float g_probs_fallback[BB * NC];
__device__ float g_ce[BB];
__device__ int   g_ctr;                          // last-softmax-row counter
__device__ int   g_done;                         // gemm+v done counter

// ============================================================================
// Kernel 1 (fused, HBM-bound, measured 26.5us @ 75.6% DRAM): pool
// inputs+attack_w 16x16 means AND reduce patch_grad over (batch, dim).
// Also resets both counters (deterministic per-call init). UNCHANGED.
// ============================================================================
#define POOL_BLOCKS (129 * CC * PN)   // 5418
#define GRAD_BLOCKS (NP * NPART)      // 3136

__global__ void k1_pool_and_reduce(const float* __restrict__ inputs,
                                   const float* __restrict__ attack_w,
                                   const float* __restrict__ patch_grad) {
    int blk = blockIdx.x;
    int t   = threadIdx.x;   // 0..223

    if (blk == 0 && t == 0) { g_ctr = 0; g_done = 0; }

    if (blk < POOL_BLOCKS) {
        int bb  = blk / (CC * PN);
        int rem = blk % (CC * PN);
        int c   = rem / PN;
        int px  = rem % PN;
        const float* src = (bb < BB)
            ? inputs   + ((size_t)(bb * CC + c) * HH + px * PS) * HH
            : attack_w + ((size_t)c * HH + px * PS) * HH;
        float acc = 0.f;
        #pragma unroll
        for (int r = 0; r < PS; ++r) acc += src[r * HH + t];
        #pragma unroll
        for (int off = 8; off > 0; off >>= 1)
            acc += __shfl_down_sync(0xffffffffu, acc, off, 16);
        if ((t & 15) == 0) {
            int iy  = t >> 4;
            float v = acc * (1.0f / 256.0f);
            int idx = c * NP + px * PN + iy;
            if (bb < BB) g_pooled_in[bb * KDIM + idx] = v;
            else         g_attack_pooled[idx]          = v;
        }
    } else {
        int gid  = blk - POOL_BLOCKS;
        int p    = gid >> 4;
        int part = gid & 15;
        int b0   = part * (BB / NPART);
        float acc = 0.f;
        if (t < DD / 4) {
            #pragma unroll
            for (int bi = 0; bi < BB / NPART; ++bi) {
                const float4 v = reinterpret_cast<const float4*>(
                    patch_grad + ((size_t)(b0 + bi) * NP + p) * DD)[t];
                acc += (v.x + v.y) + (v.z + v.w);
            }
        }
        #pragma unroll
        for (int off = 16; off > 0; off >>= 1)
            acc += __shfl_down_sync(0xffffffffu, acc, off);
        __shared__ float ws[7];
        if ((t & 31) == 0) ws[t >> 5] = acc;
        __syncthreads();
        if (t == 0) {
            float s = 0.f;
            #pragma unroll
            for (int w = 0; w < 7; ++w) s += ws[w];
            g_patch_partial[p * NPART + part] = s;
        }
    }
}

// ============================================================================
// Kernel 2 (single fused launch, 904 blocks x 128 threads, one wave):
//  bid <  768: split-K-12 SGEMM  logits_part[z] = pooled_in @ w_cls slice.
//              BM=32 x BN=64 x KT=49 (single tile), 4m x 4n per thread,
//              k-fast COALESCED gmem fills, sA padded [49][36] (4-way
//              instead of 32-way store conflict, float4 reads stay aligned).
//  bid <  776: 8 v-blocks: top-k mask + masked GEMV (batch-independent term)
//  bid >= 776: 128 softmax rows. Spin on g_done (deadlock-free: producers
//              never wait), combine 12 partials in fixed order, softmax +
//              CE + deterministic last-row loss.
// ============================================================================
#define BM 32
#define BN 64
#define BMP 36                    // BM + 4 pad: bank stride 4, rows 16B-aligned
#define GEMM_BLOCKS 768           // 16 n-tiles * 4 m-tiles * 12 z
#define VB          8
#define PROD_BLOCKS (GEMM_BLOCKS + VB)

__device__ __forceinline__ float warpMax(float v) {
    #pragma unroll
    for (int o = 16; o > 0; o >>= 1) v = fmaxf(v, __shfl_xor_sync(0xffffffffu, v, o));
    return v;
}
__device__ __forceinline__ float warpSum(float v) {
    #pragma unroll
    for (int o = 16; o > 0; o >>= 1) v += __shfl_xor_sync(0xffffffffu, v, o);
    return v;
}

__global__ void k2_fused(const float* __restrict__ w_cls,
                         const int* __restrict__ targets,
                         float* __restrict__ pdst,
                         float* __restrict__ out, int loss_idx) {
    int bid = blockIdx.x;
    int t   = threadIdx.x;   // 0..127

    if (bid < GEMM_BLOCKS) {
        __shared__ float sA[KT][BMP];  // 49x36 = 6.9 KB
        __shared__ float sW[KT][BN];   // 49x64 = 12.25 KB
        int n0 = (bid & 15) * BN;
        int m0 = ((bid >> 4) & 3) * BM;
        int z  = bid >> 6;             // 0..11
        int k0 = z * KT;
        int tn4 = (t & 15) * 4;        // 16 n-groups x 4 cols
        int tm4 = (t >> 4) * 4;        // 8 m-groups x 4 rows

        // k-fast fills: consecutive threads -> consecutive k/n (coalesced gmem)
        #pragma unroll
        for (int i = t; i < BM * KT; i += 128) {
            int m = i / KT;
            int k = i - m * KT;
            sA[k][m] = g_pooled_in[(m0 + m) * KDIM + k0 + k];
        }
        #pragma unroll
        for (int i = t; i < KT * BN; i += 128) {
            int kk = i >> 6;
            int n  = i & 63;
            int gn = n0 + n;
            sW[kk][n] = (gn < NC) ? w_cls[(size_t)(k0 + kk) * NC + gn] : 0.0f;
        }
        __syncthreads();

        float acc[4][4];
        #pragma unroll
        for (int r = 0; r < 4; ++r)
            #pragma unroll
            for (int c = 0; c < 4; ++c) acc[r][c] = 0.f;

        #pragma unroll 7
        for (int k = 0; k < KT; ++k) {
            float4 a = *(const float4*)&sA[k][tm4];
            float4 w = *(const float4*)&sW[k][tn4];
            acc[0][0] += a.x * w.x; acc[0][1] += a.x * w.y;
            acc[0][2] += a.x * w.z; acc[0][3] += a.x * w.w;
            acc[1][0] += a.y * w.x; acc[1][1] += a.y * w.y;
            acc[1][2] += a.y * w.z; acc[1][3] += a.y * w.w;
            acc[2][0] += a.z * w.x; acc[2][1] += a.z * w.y;
            acc[2][2] += a.z * w.z; acc[2][3] += a.z * w.w;
            acc[3][0] += a.w * w.x; acc[3][1] += a.w * w.y;
            acc[3][2] += a.w * w.z; acc[3][3] += a.w * w.w;
        }

        float* dst = g_logits_part[z];
        #pragma unroll
        for (int r = 0; r < 4; ++r) {
            int m = m0 + tm4 + r;
            #pragma unroll
            for (int j = 0; j < 4; ++j) {
                int n = n0 + tn4 + j;
                if (n < NC) dst[m * NC + n] = acc[r][j];
            }
        }
        __syncthreads();
        if (t == 0) { __threadfence(); atomicAdd(&g_done, 1); }
    } else if (bid < PROD_BLOCKS) {
        // ---- v-block: top-k mask + masked GEMV ----
        int vb = bid - GEMM_BLOCKS;   // 0..7
        __shared__ float         sv[NP];
        __shared__ unsigned char smask[NP];
        __shared__ int           plist[TOPK];
        for (int i = t; i < NP; i += 128) {
            float v = 0.f;
            #pragma unroll
            for (int q = 0; q < NPART; ++q) v += g_patch_partial[i * NPART + q];
            sv[i] = v;
        }
        __syncthreads();
        // rank-based top-20; ties broken by lower index (jax.lax.top_k order)
        for (int i = t; i < NP; i += 128) {
            float v = sv[i];
            int rank = 0;
            for (int j = 0; j < NP; ++j) {
                float u = sv[j];
                rank += (u > v) || (u == v && j < i);
            }
            smask[i] = (rank < TOPK) ? 1 : 0;
        }
        __syncthreads();
        if (t == 0) {                          // deterministic ascending list
            int cnt = 0;
            for (int p = 0; p < NP; ++p)
                if (smask[p] && cnt < TOPK) plist[cnt++] = p;
        }
        __syncthreads();
        int n = vb * 125 + t;                  // 8 blocks x 125 cols = 1000
        if (t < 125) {
            float acc = 0.f;
            #pragma unroll 2
            for (int i = 0; i < TOPK; ++i) {
                int p = plist[i];
                #pragma unroll
                for (int c = 0; c < CC; ++c) {
                    int k = c * NP + p;
                    acc += g_attack_pooled[k] * w_cls[(size_t)k * NC + n];
                }
            }
            g_v[n] = acc;
        }
        __syncthreads();
        if (t == 0) { __threadfence(); atomicAdd(&g_done, 1); }
    } else {
        // ---- softmax + CE for one batch row; waits for all producers ----
        int b = bid - PROD_BLOCKS;     // 0..127
        int w = t >> 5;
        __shared__ float red[4];
        __shared__ float ptgt;
        __shared__ int   slast;

        if (t == 0) {
            while (atomicAdd(&g_done, 0) < PROD_BLOCKS) __nanosleep(64);
        }
        __syncthreads();
        __threadfence();

        float l[8];
        float m = -INFINITY;
        #pragma unroll
        for (int i = 0; i < 8; ++i) {
            int j = t + i * 128;
            if (j < NC) {
                size_t o = (size_t)b * NC + j;
                float s = g_v[j];
                #pragma unroll
                for (int zz = 0; zz < SPLITK; ++zz)   // fixed order: deterministic
                    s += g_logits_part[zz][o];
                l[i] = s;
                m = fmaxf(m, l[i]);
            } else l[i] = -INFINITY;
        }
        m = warpMax(m);
        if ((t & 31) == 0) red[w] = m;
        __syncthreads();
        float rowmax = fmaxf(fmaxf(red[0], red[1]), fmaxf(red[2], red[3]));
        __syncthreads();

        float e[8]; float ssum = 0.f;
        #pragma unroll
        for (int i = 0; i < 8; ++i) {
            int j = t + i * 128;
            e[i] = (j < NC) ? __expf(l[i] - rowmax) : 0.f;
            ssum += e[i];
        }
        ssum = warpSum(ssum);
        if ((t & 31) == 0) red[w] = ssum;
        __syncthreads();
        float tot = ((red[0] + red[1]) + (red[2] + red[3]));
        float inv = 1.0f / tot;
        __syncthreads();

        int tgt = targets[b];
        float s2 = 0.f;
        #pragma unroll
        for (int i = 0; i < 8; ++i) {
            int j = t + i * 128;
            if (j < NC) {
                float p = e[i] * inv;
                pdst[(size_t)b * NC + j] = p;
                if (j == tgt) ptgt = p;
                // exp(p), p in (0,1]: degree-4 Taylor (FMA pipe, not MUFU)
                float q = fmaf(p, 1.0f / 24.0f, 1.0f / 6.0f);
                q = fmaf(p, q, 0.5f);
                q = fmaf(p, q, 1.0f);
                q = fmaf(p, q, 1.0f);
                s2 += q;
            }
        }
        s2 = warpSum(s2);
        if ((t & 31) == 0) red[w] = s2;
        __syncthreads();
        if (t == 0) {
            float tot2 = ((red[0] + red[1]) + (red[2] + red[3]));
            g_ce[b] = logf(tot2) - ptgt;
            __threadfence();
            int done = atomicAdd(&g_ctr, 1);
            slast = (done == BB - 1) ? 1 : 0;
        }
        __syncthreads();
        if (slast && t < 32 && loss_idx >= 0) {
            __threadfence();
            float s = 0.f;
            #pragma unroll
            for (int i = 0; i < 4; ++i) s += g_ce[t * 4 + i];
            #pragma unroll
            for (int off = 16; off > 0; off >>= 1)
                s += __shfl_down_sync(0xffffffffu, s, off);
            if (t == 0) out[loss_idx] = -(s * (1.0f / BB));
        }
    }
}

// ============================================================================
extern "C" void kernel_launch(void* const* d_in, const int* in_sizes, int n_in,
                              void* d_out, int out_size) {
    const float* inputs     = (const float*)d_in[0];   // [128,3,224,224]
    const float* patch_grad = (const float*)d_in[1];   // [128,196,768]
    const float* attack_w   = (const float*)d_in[2];   // [3,224,224]
    const float* w_cls      = (const float*)d_in[3];   // [588,1000]
    const int*   targets    = (const int*)d_in[4];     // [128]
    float* out = (float*)d_out;

    (void)in_sizes; (void)n_in;

    float* pdst = out;
    if (out_size < BB * NC) {
        float* fb = nullptr;
        cudaGetSymbolAddress((void**)&fb, g_probs_fallback);
        pdst = fb;
    }
    int loss_idx = -1;
    if (out_size >= BB * NC + 1)      loss_idx = BB * NC;
    else if (out_size == 1)           loss_idx = 0;

    k1_pool_and_reduce<<<POOL_BLOCKS + GRAD_BLOCKS, 224>>>(inputs, attack_w, patch_grad);
    k2_fused<<<PROD_BLOCKS + BB, 128>>>(w_cls, targets, pdst, out, loss_idx);
}

// round 16
// speedup vs baseline: 1.1190x; 1.0381x over previous
#include <cuda_runtime.h>
#include <math.h>

// Problem constants
#define BB      128
#define CC      3
#define HH      224
#define PN      14          // patches per side
#define PS      16          // patch size
#define NP      196         // PN*PN
#define DD      768
#define NC      1000
#define TOPK    20
#define KDIM    588         // C*NP
#define NPART   16          // partials for patch_grad reduction (8 batches each)
#define SPLITK  12
#define KT      49          // KDIM / SPLITK (one smem tile per block)

// -------- scratch (device globals; no runtime allocation) --------
__device__ float g_patch_partial[NP * NPART];
__device__ float g_attack_pooled[KDIM];          // c*196 + px*14 + py
__device__ float g_pooled_in[BB * KDIM];         // [b][c*196 + p]
__device__ float g_logits_part[SPLITK][BB * NC]; // split-K partials (6 MB)
__device__ float g_v[NC];                        // batch-independent mask term
__device__ float g_probs_fallback[BB * NC];
__device__ float g_ce[BB];
__device__ int   g_ctr;                          // last-softmax-row counter
__device__ int   g_done;                         // gemm+v done counter

// ============================================================================
// Kernel 1 (fused, HBM-bound, measured 26.5us @ 75.6% DRAM): pool
// inputs+attack_w 16x16 means AND reduce patch_grad over (batch, dim).
// Also resets both counters (deterministic per-call init). UNCHANGED.
// ============================================================================
#define POOL_BLOCKS (129 * CC * PN)   // 5418
#define GRAD_BLOCKS (NP * NPART)      // 3136

__global__ void k1_pool_and_reduce(const float* __restrict__ inputs,
                                   const float* __restrict__ attack_w,
                                   const float* __restrict__ patch_grad) {
    int blk = blockIdx.x;
    int t   = threadIdx.x;   // 0..223

    if (blk == 0 && t == 0) { g_ctr = 0; g_done = 0; }

    if (blk < POOL_BLOCKS) {
        int bb  = blk / (CC * PN);
        int rem = blk % (CC * PN);
        int c   = rem / PN;
        int px  = rem % PN;
        const float* src = (bb < BB)
            ? inputs   + ((size_t)(bb * CC + c) * HH + px * PS) * HH
            : attack_w + ((size_t)c * HH + px * PS) * HH;
        float acc = 0.f;
        #pragma unroll
        for (int r = 0; r < PS; ++r) acc += src[r * HH + t];
        #pragma unroll
        for (int off = 8; off > 0; off >>= 1)
            acc += __shfl_down_sync(0xffffffffu, acc, off, 16);
        if ((t & 15) == 0) {
            int iy  = t >> 4;
            float v = acc * (1.0f / 256.0f);
            int idx = c * NP + px * PN + iy;
            if (bb < BB) g_pooled_in[bb * KDIM + idx] = v;
            else         g_attack_pooled[idx]          = v;
        }
    } else {
        int gid  = blk - POOL_BLOCKS;
        int p    = gid >> 4;
        int part = gid & 15;
        int b0   = part * (BB / NPART);
        float acc = 0.f;
        if (t < DD / 4) {
            #pragma unroll
            for (int bi = 0; bi < BB / NPART; ++bi) {
                const float4 v = reinterpret_cast<const float4*>(
                    patch_grad + ((size_t)(b0 + bi) * NP + p) * DD)[t];
                acc += (v.x + v.y) + (v.z + v.w);
            }
        }
        #pragma unroll
        for (int off = 16; off > 0; off >>= 1)
            acc += __shfl_down_sync(0xffffffffu, acc, off);
        __shared__ float ws[7];
        if ((t & 31) == 0) ws[t >> 5] = acc;
        __syncthreads();
        if (t == 0) {
            float s = 0.f;
            #pragma unroll
            for (int w = 0; w < 7; ++w) s += ws[w];
            g_patch_partial[p * NPART + part] = s;
        }
    }
}

// ============================================================================
// Kernel 2 (single fused launch, 904 blocks x 128 threads, one wave):
//  __launch_bounds__(128, 8): pins the ptxas register budget at 64/thread so
//  the 4x4 accumulator tile stays in registers (R13-R15 showed ptxas's
//  occupancy heuristic picking 32-104 regs run-to-run; at 32 the accumulators
//  spill to local -> the invariant ~32us and high L1%). 8 blocks/SM also
//  keeps the whole grid one co-resident wave (19.6KB smem x 8 = 157KB).
//
//  bid <  768: split-K-12 SGEMM  logits_part[z] = pooled_in @ w_cls slice.
//              BM=32 x BN=64 x KT=49 (single tile), 4m x 4n per thread,
//              k-fast COALESCED gmem fills, sA padded [49][36].
//  bid <  776: 8 v-blocks: top-k mask + masked GEMV (batch-independent term)
//  bid >= 776: 128 softmax rows. Volatile-load spin on g_done (producers
//              never wait -> deadlock-free; no atomic-queue pollution),
//              combine 12 partials fixed-order, softmax + CE + last-row loss.
// ============================================================================
#define BM 32
#define BN 64
#define BMP 36                    // BM + 4 pad: bank stride 4, rows 16B-aligned
#define GEMM_BLOCKS 768           // 16 n-tiles * 4 m-tiles * 12 z
#define VB          8
#define PROD_BLOCKS (GEMM_BLOCKS + VB)

__device__ __forceinline__ float warpMax(float v) {
    #pragma unroll
    for (int o = 16; o > 0; o >>= 1) v = fmaxf(v, __shfl_xor_sync(0xffffffffu, v, o));
    return v;
}
__device__ __forceinline__ float warpSum(float v) {
    #pragma unroll
    for (int o = 16; o > 0; o >>= 1) v += __shfl_xor_sync(0xffffffffu, v, o);
    return v;
}

__global__ void __launch_bounds__(128, 8)
k2_fused(const float* __restrict__ w_cls,
         const int* __restrict__ targets,
         float* __restrict__ pdst,
         float* __restrict__ out, int loss_idx) {
    int bid = blockIdx.x;
    int t   = threadIdx.x;   // 0..127

    if (bid < GEMM_BLOCKS) {
        __shared__ float sA[KT][BMP];  // 49x36 = 6.9 KB
        __shared__ float sW[KT][BN];   // 49x64 = 12.25 KB
        int n0 = (bid & 15) * BN;
        int m0 = ((bid >> 4) & 3) * BM;
        int z  = bid >> 6;             // 0..11
        int k0 = z * KT;
        int tn4 = (t & 15) * 4;        // 16 n-groups x 4 cols
        int tm4 = (t >> 4) * 4;        // 8 m-groups x 4 rows

        // k-fast fills: consecutive threads -> consecutive k/n (coalesced gmem)
        for (int i = t; i < BM * KT; i += 128) {
            int m = i / KT;
            int k = i - m * KT;
            sA[k][m] = g_pooled_in[(m0 + m) * KDIM + k0 + k];
        }
        for (int i = t; i < KT * BN; i += 128) {
            int kk = i >> 6;
            int n  = i & 63;
            int gn = n0 + n;
            sW[kk][n] = (gn < NC) ? w_cls[(size_t)(k0 + kk) * NC + gn] : 0.0f;
        }
        __syncthreads();

        float acc[4][4];
        #pragma unroll
        for (int r = 0; r < 4; ++r)
            #pragma unroll
            for (int c = 0; c < 4; ++c) acc[r][c] = 0.f;

        #pragma unroll 7
        for (int k = 0; k < KT; ++k) {
            float4 a = *(const float4*)&sA[k][tm4];
            float4 w = *(const float4*)&sW[k][tn4];
            acc[0][0] += a.x * w.x; acc[0][1] += a.x * w.y;
            acc[0][2] += a.x * w.z; acc[0][3] += a.x * w.w;
            acc[1][0] += a.y * w.x; acc[1][1] += a.y * w.y;
            acc[1][2] += a.y * w.z; acc[1][3] += a.y * w.w;
            acc[2][0] += a.z * w.x; acc[2][1] += a.z * w.y;
            acc[2][2] += a.z * w.z; acc[2][3] += a.z * w.w;
            acc[3][0] += a.w * w.x; acc[3][1] += a.w * w.y;
            acc[3][2] += a.w * w.z; acc[3][3] += a.w * w.w;
        }

        float* dst = g_logits_part[z];
        #pragma unroll
        for (int r = 0; r < 4; ++r) {
            int m = m0 + tm4 + r;
            #pragma unroll
            for (int j = 0; j < 4; ++j) {
                int n = n0 + tn4 + j;
                if (n < NC) dst[m * NC + n] = acc[r][j];
            }
        }
        __syncthreads();
        if (t == 0) { __threadfence(); atomicAdd(&g_done, 1); }
    } else if (bid < PROD_BLOCKS) {
        // ---- v-block: top-k mask + masked GEMV ----
        int vb = bid - GEMM_BLOCKS;   // 0..7
        __shared__ float         sv[NP];
        __shared__ unsigned char smask[NP];
        __shared__ int           plist[TOPK];
        for (int i = t; i < NP; i += 128) {
            float v = 0.f;
            #pragma unroll
            for (int q = 0; q < NPART; ++q) v += g_patch_partial[i * NPART + q];
            sv[i] = v;
        }
        __syncthreads();
        // rank-based top-20; ties broken by lower index (jax.lax.top_k order)
        for (int i = t; i < NP; i += 128) {
            float v = sv[i];
            int rank = 0;
            for (int j = 0; j < NP; ++j) {
                float u = sv[j];
                rank += (u > v) || (u == v && j < i);
            }
            smask[i] = (rank < TOPK) ? 1 : 0;
        }
        __syncthreads();
        if (t == 0) {                          // deterministic ascending list
            int cnt = 0;
            for (int p = 0; p < NP; ++p)
                if (smask[p] && cnt < TOPK) plist[cnt++] = p;
        }
        __syncthreads();
        int n = vb * 125 + t;                  // 8 blocks x 125 cols = 1000
        if (t < 125) {
            float acc = 0.f;
            #pragma unroll 2
            for (int i = 0; i < TOPK; ++i) {
                int p = plist[i];
                #pragma unroll
                for (int c = 0; c < CC; ++c) {
                    int k = c * NP + p;
                    acc += g_attack_pooled[k] * w_cls[(size_t)k * NC + n];
                }
            }
            g_v[n] = acc;
        }
        __syncthreads();
        if (t == 0) { __threadfence(); atomicAdd(&g_done, 1); }
    } else {
        // ---- softmax + CE for one batch row; waits for all producers ----
        int b = bid - PROD_BLOCKS;     // 0..127
        int w = t >> 5;
        __shared__ float red[4];
        __shared__ float ptgt;
        __shared__ int   slast;

        if (t == 0) {
            volatile int* dp = &g_done;    // plain loads: no atomic-queue traffic
            while (*dp < PROD_BLOCKS) __nanosleep(128);
        }
        __syncthreads();
        __threadfence();

        float l[8];
        float m = -INFINITY;
        #pragma unroll
        for (int i = 0; i < 8; ++i) {
            int j = t + i * 128;
            if (j < NC) {
                size_t o = (size_t)b * NC + j;
                float s = g_v[j];
                #pragma unroll
                for (int zz = 0; zz < SPLITK; ++zz)   // fixed order: deterministic
                    s += g_logits_part[zz][o];
                l[i] = s;
                m = fmaxf(m, l[i]);
            } else l[i] = -INFINITY;
        }
        m = warpMax(m);
        if ((t & 31) == 0) red[w] = m;
        __syncthreads();
        float rowmax = fmaxf(fmaxf(red[0], red[1]), fmaxf(red[2], red[3]));
        __syncthreads();

        float e[8]; float ssum = 0.f;
        #pragma unroll
        for (int i = 0; i < 8; ++i) {
            int j = t + i * 128;
            e[i] = (j < NC) ? __expf(l[i] - rowmax) : 0.f;
            ssum += e[i];
        }
        ssum = warpSum(ssum);
        if ((t & 31) == 0) red[w] = ssum;
        __syncthreads();
        float tot = ((red[0] + red[1]) + (red[2] + red[3]));
        float inv = 1.0f / tot;
        __syncthreads();

        int tgt = targets[b];
        float s2 = 0.f;
        #pragma unroll
        for (int i = 0; i < 8; ++i) {
            int j = t + i * 128;
            if (j < NC) {
                float p = e[i] * inv;
                pdst[(size_t)b * NC + j] = p;
                if (j == tgt) ptgt = p;
                // exp(p), p in (0,1]: degree-4 Taylor (FMA pipe, not MUFU)
                float q = fmaf(p, 1.0f / 24.0f, 1.0f / 6.0f);
                q = fmaf(p, q, 0.5f);
                q = fmaf(p, q, 1.0f);
                q = fmaf(p, q, 1.0f);
                s2 += q;
            }
        }
        s2 = warpSum(s2);
        if ((t & 31) == 0) red[w] = s2;
        __syncthreads();
        if (t == 0) {
            float tot2 = ((red[0] + red[1]) + (red[2] + red[3]));
            g_ce[b] = logf(tot2) - ptgt;
            __threadfence();
            int done = atomicAdd(&g_ctr, 1);
            slast = (done == BB - 1) ? 1 : 0;
        }
        __syncthreads();
        if (slast && t < 32 && loss_idx >= 0) {
            __threadfence();
            float s = 0.f;
            #pragma unroll
            for (int i = 0; i < 4; ++i) s += g_ce[t * 4 + i];
            #pragma unroll
            for (int off = 16; off > 0; off >>= 1)
                s += __shfl_down_sync(0xffffffffu, s, off);
            if (t == 0) out[loss_idx] = -(s * (1.0f / BB));
        }
    }
}

// ============================================================================
extern "C" void kernel_launch(void* const* d_in, const int* in_sizes, int n_in,
                              void* d_out, int out_size) {
    const float* inputs     = (const float*)d_in[0];   // [128,3,224,224]
    const float* patch_grad = (const float*)d_in[1];   // [128,196,768]
    const float* attack_w   = (const float*)d_in[2];   // [3,224,224]
    const float* w_cls      = (const float*)d_in[3];   // [588,1000]
    const int*   targets    = (const int*)d_in[4];     // [128]
    float* out = (float*)d_out;

    (void)in_sizes; (void)n_in;

    float* pdst = out;
    if (out_size < BB * NC) {
        float* fb = nullptr;
        cudaGetSymbolAddress((void**)&fb, g_probs_fallback);
        pdst = fb;
    }
    int loss_idx = -1;
    if (out_size >= BB * NC + 1)      loss_idx = BB * NC;
    else if (out_size == 1)           loss_idx = 0;

    k1_pool_and_reduce<<<POOL_BLOCKS + GRAD_BLOCKS, 224>>>(inputs, attack_w, patch_grad);
    k2_fused<<<PROD_BLOCKS + BB, 128>>>(w_cls, targets, pdst, out, loss_idx);
}